// round 4
// baseline (speedup 1.0000x reference)
#include <cuda_runtime.h>
#include <cuda_bf16.h>
#include <cstdint>

// ---------------------------------------------------------------------------
// Problem constants
// ---------------------------------------------------------------------------
constexpr int BATCH = 2;
constexpr int NPTS  = 4096;
constexpr int KNN_K = 16;
constexpr int C     = 128;
constexpr int CIN   = 64;
constexpr int GRP   = 8;
constexpr int LBIG  = NPTS * KNN_K;   // 65536
constexpr float GN_EPS = 1e-5f;
constexpr float GN_INVCOUNT = 1.0f / (16.0f * NPTS * KNN_K);
constexpr int PK = 40;                // X smem pitch (80B: odd 16B multiple -> conflict-free)
constexpr int PW = 136;               // W smem pitch (272B: odd 16B multiple -> conflict-free)
constexpr int TG_SMEM = (2 * 128 * PW + 4 * 128 * PK) * 2;   // 110592 bytes

// ---------------------------------------------------------------------------
// Scratch (device globals; allocation-free per harness rules)
// ---------------------------------------------------------------------------
__device__ float g_feat1T[BATCH * NPTS * CIN];
__device__ float g_feat2T[BATCH * NPTS * CIN];
__device__ float g_f1T[BATCH * NPTS * C];
__device__ float g_f2T[BATCH * NPTS * C];
__device__ float g_g1T[BATCH * NPTS * C];
__device__ float g_g2T[BATCH * NPTS * C];
__device__ float g_f1nT[BATCH * NPTS * C];
__device__ float g_f2nT[BATCH * NPTS * C];
__device__ float g_cross[BATCH * NPTS * C];
__device__ int   g_idx12[BATCH * NPTS * KNN_K];
__device__ int   g_idx21[BATCH * NPTS * KNN_K];
__device__ float g_XA[(size_t)BATCH * LBIG * C];   // 64 MB
__device__ float g_XB[(size_t)BATCH * LBIG * C];   // 64 MB
__device__ float g_stats[8 * BATCH * GRP * 2];
__device__ float g_sb[8 * BATCH * C * 2];

__global__ void zero_stats_kernel() {
    int i = threadIdx.x;
    g_stats[i] = 0.0f;
}

// ---------------------------------------------------------------------------
// Transpose [B][CIN][N] -> [B][N][CIN]
// ---------------------------------------------------------------------------
__global__ void transpose64_kernel(const float* __restrict__ in, float* __restrict__ out) {
    int i = blockIdx.x * 256 + threadIdx.x;
    int c = i & 63;
    int n = (i >> 6) & (NPTS - 1);
    int b = i >> 18;
    out[i] = __ldg(&in[((size_t)b * CIN + c) * NPTS + n]);
}

// ---------------------------------------------------------------------------
// Transpose [B][N][C] -> [B][C][N]
// ---------------------------------------------------------------------------
__global__ void lc2cl_kernel(const float* __restrict__ in, float* __restrict__ out) {
    __shared__ float t[32][33];
    int b = blockIdx.z;
    int n0 = blockIdx.x * 32, c0 = blockIdx.y * 32;
    int x = threadIdx.x, y = threadIdx.y;   // 32 x 8
    #pragma unroll
    for (int i = 0; i < 32; i += 8)
        t[y + i][x] = in[((size_t)b * NPTS + n0 + y + i) * C + c0 + x];
    __syncthreads();
    #pragma unroll
    for (int i = 0; i < 32; i += 8)
        out[(size_t)b * C * NPTS + (size_t)(c0 + y + i) * NPTS + n0 + x] = t[x][y + i];
}

// ---------------------------------------------------------------------------
// KNN
// ---------------------------------------------------------------------------
__device__ __forceinline__ unsigned long long knn_key(float d, int j) {
    unsigned u = __float_as_uint(d);
    u = (u & 0x80000000u) ? ~u : (u | 0x80000000u);
    return ((unsigned long long)u << 32) | (unsigned)j;
}

__global__ void knn_kernel(const float* __restrict__ xyzQ,
                           const float* __restrict__ xyzD,
                           int* __restrict__ out) {
    __shared__ unsigned long long wred[8];
    __shared__ unsigned long long swin;
    int n = blockIdx.x, b = blockIdx.y, tid = threadIdx.x;
    const float* Q = xyzQ + (size_t)b * 3 * NPTS;
    const float* D = xyzD + (size_t)b * 3 * NPTS;
    float qx = Q[n], qy = Q[NPTS + n], qz = Q[2 * NPTS + n];
    float s1 = qx * qx + qy * qy + qz * qz;

    float myd[16];
    #pragma unroll
    for (int i = 0; i < 16; i++) {
        int j = tid + (i << 8);
        float px = D[j], py = D[NPTS + j], pz = D[2 * NPTS + j];
        float dot = qx * px + qy * py + qz * pz;
        float s2 = px * px + py * py + pz * pz;
        myd[i] = s1 + s2 - 2.0f * dot;
    }
    unsigned long long localbest = ~0ull;
    #pragma unroll
    for (int i = 0; i < 16; i++)
        localbest = min(localbest, knn_key(myd[i], tid + (i << 8)));

    for (int r = 0; r < KNN_K; r++) {
        unsigned long long best = localbest;
        #pragma unroll
        for (int off = 16; off; off >>= 1)
            best = min(best, __shfl_down_sync(0xffffffffu, best, off));
        if ((tid & 31) == 0) wred[tid >> 5] = best;
        __syncthreads();
        if (tid == 0) {
            unsigned long long m = wred[0];
            #pragma unroll
            for (int i = 1; i < 8; i++) m = min(m, wred[i]);
            swin = m;
            out[((size_t)b * NPTS + n) * KNN_K + r] = (int)(m & 0xffffffffu);
        }
        __syncthreads();
        int jwin = (int)(swin & 0xffffffffu);
        if ((jwin & 255) == tid) {
            int k = jwin >> 8;
            #pragma unroll
            for (int i = 0; i < 16; i++) if (i == k) myd[i] = __int_as_float(0x7f800000);
            localbest = ~0ull;
            #pragma unroll
            for (int i = 0; i < 16; i++)
                localbest = min(localbest, knn_key(myd[i], tid + (i << 8)));
        }
    }
}

// ---------------------------------------------------------------------------
// Assemble: X0[b][n*16+k][c] = p2T[idx] + p1T[n] + pos(dir), + group stats
// ---------------------------------------------------------------------------
__global__ void assemble_kernel(const float* __restrict__ xyz1,
                                const float* __restrict__ xyz2,
                                const float* __restrict__ p1T,
                                const float* __restrict__ p2T,
                                const int* __restrict__ idx,
                                const float* __restrict__ posw,
                                const float* __restrict__ posb,
                                float* __restrict__ X0,
                                float* __restrict__ stats) {
    __shared__ float sdx[16], sdy[16], sdz[16];
    __shared__ int sj[16];
    __shared__ float rs[128], rq[128];
    int c = threadIdx.x;
    int b = blockIdx.y;
    int nbase = blockIdx.x * 32;
    float pwx = posw[c * 3 + 0], pwy = posw[c * 3 + 1], pwz = posw[c * 3 + 2];
    float pb = posb[c];
    float lsum = 0.f, lsq = 0.f;
    const float* x1 = xyz1 + (size_t)b * 3 * NPTS;
    const float* x2 = xyz2 + (size_t)b * 3 * NPTS;
    for (int np = 0; np < 32; np++) {
        int n = nbase + np;
        __syncthreads();
        if (c < 16) {
            int j = idx[((size_t)b * NPTS + n) * KNN_K + c];
            sj[c] = j;
            sdx[c] = x2[j]            - x1[n];
            sdy[c] = x2[NPTS + j]     - x1[NPTS + n];
            sdz[c] = x2[2 * NPTS + j] - x1[2 * NPTS + n];
        }
        __syncthreads();
        float p1v = p1T[((size_t)b * NPTS + n) * C + c];
        #pragma unroll
        for (int k = 0; k < KNN_K; k++) {
            float v = p2T[((size_t)b * NPTS + sj[k]) * C + c] + p1v +
                      pwx * sdx[k] + pwy * sdy[k] + pwz * sdz[k] + pb;
            X0[(((size_t)b * NPTS + n) * KNN_K + k) * C + c] = v;
            lsum += v; lsq += v * v;
        }
    }
    rs[c] = lsum; rq[c] = lsq;
    __syncthreads();
    #pragma unroll
    for (int off = 8; off > 0; off >>= 1) {
        if ((c & 15) < off) { rs[c] += rs[c + off]; rq[c] += rq[c + off]; }
        __syncthreads();
    }
    if ((c & 15) == 0) {
        int g = c >> 4;
        atomicAdd(&stats[(b * GRP + g) * 2 + 0], rs[c]);
        atomicAdd(&stats[(b * GRP + g) * 2 + 1], rq[c]);
    }
}

// ---------------------------------------------------------------------------
// Finalize GN stats -> per-channel (scale, bias)
// ---------------------------------------------------------------------------
__global__ void finalize_kernel(const float* __restrict__ stats,
                                const float* __restrict__ gamma,
                                const float* __restrict__ beta,
                                float* __restrict__ sb,
                                float invcount) {
    int i = threadIdx.x;              // 256 = B*C
    int b = i >> 7, c = i & 127, g = c >> 4;
    float sum = stats[(b * GRP + g) * 2 + 0];
    float sq  = stats[(b * GRP + g) * 2 + 1];
    float mean = sum * invcount;
    float var  = sq * invcount - mean * mean;
    float s = gamma[c] * rsqrtf(var + GN_EPS);
    sb[i * 2 + 0] = s;
    sb[i * 2 + 1] = beta[c] - mean * s;
}

// ---------------------------------------------------------------------------
// Tensor-core GEMM (bf16 split, pipelined, W resident in smem)
// ---------------------------------------------------------------------------
__device__ __forceinline__ void ldm4(uint32_t r[4], const __nv_bfloat16* p) {
    uint32_t a = (uint32_t)__cvta_generic_to_shared(p);
    asm volatile("ldmatrix.sync.aligned.m8n8.x4.shared.b16 {%0,%1,%2,%3}, [%4];"
                 : "=r"(r[0]), "=r"(r[1]), "=r"(r[2]), "=r"(r[3]) : "r"(a));
}
__device__ __forceinline__ void mma16816(float c[4], const uint32_t a[4], const uint32_t* b) {
    asm volatile("mma.sync.aligned.m16n8k16.row.col.f32.bf16.bf16.f32 "
                 "{%0,%1,%2,%3}, {%4,%5,%6,%7}, {%8,%9}, {%0,%1,%2,%3};"
                 : "+f"(c[0]), "+f"(c[1]), "+f"(c[2]), "+f"(c[3])
                 : "r"(a[0]), "r"(a[1]), "r"(a[2]), "r"(a[3]), "r"(b[0]), "r"(b[1]));
}
// split two fp32 into packed bf16x2 hi + bf16x2 lo (residual)
__device__ __forceinline__ void cvt_split2(float x0, float x1, uint32_t& hi2, uint32_t& lo2) {
    asm("cvt.rn.bf16x2.f32 %0, %1, %2;" : "=r"(hi2) : "f"(x1), "f"(x0));
    float h0 = __uint_as_float(hi2 << 16);
    float h1 = __uint_as_float(hi2 & 0xffff0000u);
    asm("cvt.rn.bf16x2.f32 %0, %1, %2;" : "=r"(lo2) : "f"(x1 - h1), "f"(x0 - h0));
}

__global__ __launch_bounds__(256)
void tgemm_kernel(const float* __restrict__ W, const float* __restrict__ bias,
                  const float* __restrict__ X, float* __restrict__ outLC,
                  const float* __restrict__ sb, float* __restrict__ stats,
                  int L, int KD) {
    extern __shared__ __align__(16) unsigned char dyn[];
    __nv_bfloat16* wh = (__nv_bfloat16*)dyn;
    __nv_bfloat16* wl = wh + 128 * PW;
    __nv_bfloat16* xbase = wl + 128 * PW;        // 4 tiles of 128*PK (dbl-buffered hi/lo)
    float* stage = (float*)xbase;                // epilogue staging (33.8KB <= 40.96KB)
    __shared__ float sgrp[GRP][2];
    __shared__ float ssb[2 * C];

    int tid = threadIdx.x;
    int lane = tid & 31, w = tid >> 5;
    int bb = blockIdx.y;
    int l0 = blockIdx.x * 128;
    int warpM = (w >> 1) * 32;
    int warpL = (w & 1) * 64;

    const float* Xb = X + (size_t)bb * L * KD;

    if (tid < 2 * GRP) ((float*)sgrp)[tid] = 0.f;
    if (sb) {
        if (tid < 2 * C) ssb[tid] = sb[bb * C * 2 + tid];
    }

    int lrow = tid >> 1;
    int colq = (tid & 1) * 16;

    // ---- W: load + convert resident tiles (hi/lo), once ----
    for (int c0 = 0; c0 < KD; c0 += 32) {
        const float* wsrc = W + (size_t)lrow * KD + c0 + colq;
        float4 v0 = *(const float4*)(wsrc);
        float4 v1 = *(const float4*)(wsrc + 4);
        float4 v2 = *(const float4*)(wsrc + 8);
        float4 v3 = *(const float4*)(wsrc + 12);
        float vv[16] = {v0.x, v0.y, v0.z, v0.w, v1.x, v1.y, v1.z, v1.w,
                        v2.x, v2.y, v2.z, v2.w, v3.x, v3.y, v3.z, v3.w};
        int off = lrow * PW + c0 + colq;
        #pragma unroll
        for (int p = 0; p < 8; p++) {
            uint32_t h2, l2;
            cvt_split2(vv[2 * p], vv[2 * p + 1], h2, l2);
            *(uint32_t*)(wh + off + 2 * p) = h2;
            *(uint32_t*)(wl + off + 2 * p) = l2;
        }
    }

    float acc[2][8][4];
    #pragma unroll
    for (int mt = 0; mt < 2; mt++)
        #pragma unroll
        for (int nt = 0; nt < 8; nt++)
            #pragma unroll
            for (int q = 0; q < 4; q++) acc[mt][nt][q] = 0.f;

    // ldmatrix per-lane row/col offsets
    int rA = (lane & 7) + ((lane >> 3) & 1) * 8;
    int cA = ((lane >> 4) & 1) * 8;
    int rB = (lane & 7) + ((lane >> 4) & 1) * 8;
    int cB = ((lane >> 3) & 1) * 8;

    int nck = KD / 32;
    float xr[16];
    {   // prefetch chunk 0
        const float* xs = Xb + (size_t)(l0 + lrow) * KD + colq;
        float4 a = *(const float4*)xs, b2 = *(const float4*)(xs + 4),
               c2 = *(const float4*)(xs + 8), d2 = *(const float4*)(xs + 12);
        xr[0]=a.x; xr[1]=a.y; xr[2]=a.z; xr[3]=a.w; xr[4]=b2.x; xr[5]=b2.y; xr[6]=b2.z; xr[7]=b2.w;
        xr[8]=c2.x; xr[9]=c2.y; xr[10]=c2.z; xr[11]=c2.w; xr[12]=d2.x; xr[13]=d2.y; xr[14]=d2.z; xr[15]=d2.w;
    }

    int buf = 0;
    for (int ci = 0; ci < nck; ci++) {
        __nv_bfloat16* xh = xbase + buf * (2 * 128 * PK);
        __nv_bfloat16* xl = xh + 128 * PK;
        // ---- convert prefetched chunk (+GN+lrelu) into smem ----
        {
            int cbase = ci * 32 + colq;
            if (sb) {
                #pragma unroll
                for (int q = 0; q < 16; q++) {
                    float2 t = *(const float2*)&ssb[(cbase + q) * 2];
                    float y = xr[q] * t.x + t.y;
                    xr[q] = fmaxf(y, 0.1f * y);
                }
            }
            int off = lrow * PK + colq;
            #pragma unroll
            for (int p = 0; p < 8; p++) {
                uint32_t h2, l2;
                cvt_split2(xr[2 * p], xr[2 * p + 1], h2, l2);
                *(uint32_t*)(xh + off + 2 * p) = h2;
                *(uint32_t*)(xl + off + 2 * p) = l2;
            }
        }
        __syncthreads();
        // ---- prefetch next chunk (LDG latency hides behind MMAs) ----
        if (ci + 1 < nck) {
            const float* xs = Xb + (size_t)(l0 + lrow) * KD + (ci + 1) * 32 + colq;
            float4 a = *(const float4*)xs, b2 = *(const float4*)(xs + 4),
                   c2 = *(const float4*)(xs + 8), d2 = *(const float4*)(xs + 12);
            xr[0]=a.x; xr[1]=a.y; xr[2]=a.z; xr[3]=a.w; xr[4]=b2.x; xr[5]=b2.y; xr[6]=b2.z; xr[7]=b2.w;
            xr[8]=c2.x; xr[9]=c2.y; xr[10]=c2.z; xr[11]=c2.w; xr[12]=d2.x; xr[13]=d2.y; xr[14]=d2.z; xr[15]=d2.w;
        }
        // ---- MMAs for this chunk ----
        #pragma unroll
        for (int s = 0; s < 2; s++) {
            int c0 = ci * 32 + s * 16;
            uint32_t ah[2][4], al[2][4];
            #pragma unroll
            for (int mt = 0; mt < 2; mt++) {
                ldm4(ah[mt], wh + (warpM + mt * 16 + rA) * PW + c0 + cA);
                ldm4(al[mt], wl + (warpM + mt * 16 + rA) * PW + c0 + cA);
            }
            #pragma unroll
            for (int np = 0; np < 4; np++) {
                uint32_t bh[4], bl[4];
                ldm4(bh, xh + (warpL + np * 16 + rB) * PK + s * 16 + cB);
                ldm4(bl, xl + (warpL + np * 16 + rB) * PK + s * 16 + cB);
                #pragma unroll
                for (int mt = 0; mt < 2; mt++) {
                    #pragma unroll
                    for (int sub = 0; sub < 2; sub++) {
                        int nt = np * 2 + sub;
                        mma16816(acc[mt][nt], ah[mt], &bh[sub * 2]);
                        mma16816(acc[mt][nt], ah[mt], &bl[sub * 2]);
                        mma16816(acc[mt][nt], al[mt], &bh[sub * 2]);
                    }
                }
            }
        }
        buf ^= 1;
    }

    // ---- epilogue: bias, stats ----
    #pragma unroll
    for (int mt = 0; mt < 2; mt++) {
        float b0 = __ldg(&bias[warpM + mt * 16 + (lane >> 2)]);
        float b1 = __ldg(&bias[warpM + mt * 16 + (lane >> 2) + 8]);
        float lsum = 0.f, lsq = 0.f;
        #pragma unroll
        for (int nt = 0; nt < 8; nt++) {
            acc[mt][nt][0] += b0; acc[mt][nt][1] += b0;
            acc[mt][nt][2] += b1; acc[mt][nt][3] += b1;
            if (stats) {
                #pragma unroll
                for (int q = 0; q < 4; q++) {
                    float v = acc[mt][nt][q];
                    lsum += v; lsq += v * v;
                }
            }
        }
        if (stats) {
            #pragma unroll
            for (int off = 16; off; off >>= 1) {
                lsum += __shfl_down_sync(0xffffffffu, lsum, off);
                lsq  += __shfl_down_sync(0xffffffffu, lsq, off);
            }
            if (lane == 0) {
                int g = (warpM + mt * 16) >> 4;
                atomicAdd(&sgrp[g][0], lsum);
                atomicAdd(&sgrp[g][1], lsq);
            }
        }
    }

    // ---- store via smem stage (two L-halves), coalesced float4 ----
    #pragma unroll
    for (int p = 0; p < 2; p++) {
        __syncthreads();
        if ((w & 1) == p) {
            #pragma unroll
            for (int mt = 0; mt < 2; mt++) {
                int oc = warpM + mt * 16 + (lane >> 2);
                #pragma unroll
                for (int nt = 0; nt < 8; nt++) {
                    int lc = nt * 8 + (lane & 3) * 2;
                    stage[(lc + 0) * 132 + oc]     = acc[mt][nt][0];
                    stage[(lc + 1) * 132 + oc]     = acc[mt][nt][1];
                    stage[(lc + 0) * 132 + oc + 8] = acc[mt][nt][2];
                    stage[(lc + 1) * 132 + oc + 8] = acc[mt][nt][3];
                }
            }
        }
        __syncthreads();
        int lr = tid >> 2;
        int q0 = (tid & 3) * 8;
        float* dst = outLC + ((size_t)bb * L + l0 + p * 64 + lr) * C;
        #pragma unroll
        for (int i = 0; i < 8; i++)
            *(float4*)(dst + (q0 + i) * 4) = *(const float4*)(stage + lr * 132 + (q0 + i) * 4);
    }

    if (stats && tid < GRP) {
        atomicAdd(&stats[(bb * GRP + tid) * 2 + 0], sgrp[tid][0]);
        atomicAdd(&stats[(bb * GRP + tid) * 2 + 1], sgrp[tid][1]);
    }
}

// ---------------------------------------------------------------------------
// Maxpool over k with fused GN + lrelu; outLC and/or outCL
// ---------------------------------------------------------------------------
__global__ void maxpool_kernel(const float* __restrict__ X,
                               const float* __restrict__ sb,
                               float* __restrict__ outLC,
                               float* __restrict__ outCL) {
    __shared__ float tile[32][129];
    int c = threadIdx.x;
    int b = blockIdx.y;
    int n0 = blockIdx.x * 32;
    float s  = sb[((size_t)b * C + c) * 2 + 0];
    float bb = sb[((size_t)b * C + c) * 2 + 1];
    for (int np = 0; np < 32; np++) {
        int n = n0 + np;
        float acc = -3.4e38f;
        #pragma unroll
        for (int k = 0; k < KNN_K; k++) {
            float v = X[(((size_t)b * NPTS + n) * KNN_K + k) * C + c];
            v = v * s + bb;
            v = fmaxf(v, 0.1f * v);
            acc = fmaxf(acc, v);
        }
        if (outLC) outLC[((size_t)b * NPTS + n) * C + c] = acc;
        tile[np][c] = acc;
    }
    __syncthreads();
    if (outCL) {
        int w = c >> 5, lane = c & 31;
        #pragma unroll
        for (int i = 0; i < 32; i++) {
            int ch = w + i * 4;
            outCL[(size_t)b * C * NPTS + (size_t)ch * NPTS + n0 + lane] = tile[lane][ch];
        }
    }
}

// ---------------------------------------------------------------------------
// Host orchestration
// ---------------------------------------------------------------------------
static inline float* fsym(const void* p) { return (float*)p; }

extern "C" void kernel_launch(void* const* d_in, const int* in_sizes, int n_in,
                              void* d_out, int out_size) {
    const float* pc1    = (const float*)d_in[0];
    const float* pc2    = (const float*)d_in[1];
    const float* feat1  = (const float*)d_in[2];
    const float* feat2  = (const float*)d_in[3];
    const float* t11_w  = (const float*)d_in[4];
    const float* t11_b  = (const float*)d_in[5];
    const float* t22_w  = (const float*)d_in[6];
    const float* t22_b  = (const float*)d_in[7];
    const float* pos1_w = (const float*)d_in[8];
    const float* pos1_b = (const float*)d_in[9];
    const float* gn1_g  = (const float*)d_in[10];
    const float* gn1_b  = (const float*)d_in[11];
    const float* m1a_w  = (const float*)d_in[12];
    const float* m1a_b  = (const float*)d_in[13];
    const float* m1a_g  = (const float*)d_in[14];
    const float* m1a_bt = (const float*)d_in[15];
    const float* m1b_w  = (const float*)d_in[16];
    const float* m1b_b  = (const float*)d_in[17];
    const float* m1b_g  = (const float*)d_in[18];
    const float* m1b_bt = (const float*)d_in[19];
    const float* t1_w   = (const float*)d_in[20];
    const float* t1_b   = (const float*)d_in[21];
    const float* t2_w   = (const float*)d_in[22];
    const float* t2_b   = (const float*)d_in[23];
    const float* pos2_w = (const float*)d_in[24];
    const float* pos2_b = (const float*)d_in[25];
    const float* gn2_g  = (const float*)d_in[26];
    const float* gn2_b  = (const float*)d_in[27];
    const float* m2a_w  = (const float*)d_in[28];
    const float* m2a_b  = (const float*)d_in[29];
    const float* m2a_g  = (const float*)d_in[30];
    const float* m2a_bt = (const float*)d_in[31];
    float* out = (float*)d_out;

    static int smem_set = 0;
    if (!smem_set) {
        cudaFuncSetAttribute(tgemm_kernel, cudaFuncAttributeMaxDynamicSharedMemorySize, TG_SMEM);
        smem_set = 1;
    }

    void *pA, *pB, *pF1T, *pF2T, *pf1, *pf2, *pg1, *pg2, *pf1n, *pf2n,
         *pcross, *pi12, *pi21, *pstats, *psb;
    cudaGetSymbolAddress(&pA, g_XA);
    cudaGetSymbolAddress(&pB, g_XB);
    cudaGetSymbolAddress(&pF1T, g_feat1T);
    cudaGetSymbolAddress(&pF2T, g_feat2T);
    cudaGetSymbolAddress(&pf1, g_f1T);
    cudaGetSymbolAddress(&pf2, g_f2T);
    cudaGetSymbolAddress(&pg1, g_g1T);
    cudaGetSymbolAddress(&pg2, g_g2T);
    cudaGetSymbolAddress(&pf1n, g_f1nT);
    cudaGetSymbolAddress(&pf2n, g_f2nT);
    cudaGetSymbolAddress(&pcross, g_cross);
    cudaGetSymbolAddress(&pi12, g_idx12);
    cudaGetSymbolAddress(&pi21, g_idx21);
    cudaGetSymbolAddress(&pstats, g_stats);
    cudaGetSymbolAddress(&psb, g_sb);

    float* XA = fsym(pA);  float* XB = fsym(pB);
    float* feat1T = fsym(pF1T); float* feat2T = fsym(pF2T);
    float* f1T = fsym(pf1); float* f2T = fsym(pf2);
    float* g1T = fsym(pg1); float* g2T = fsym(pg2);
    float* f1nT = fsym(pf1n); float* f2nT = fsym(pf2n);
    float* crossT = fsym(pcross);
    int* idx12 = (int*)pi12; int* idx21 = (int*)pi21;
    float* stats = fsym(pstats);
    float* sb = fsym(psb);

    const size_t BCN = (size_t)BATCH * C * NPTS;

    auto STAT = [&](int s) { return stats + s * BATCH * GRP * 2; };
    auto SB   = [&](int s) { return sb + s * BATCH * C * 2; };

    dim3 gridBig(LBIG / 128, BATCH);
    dim3 gridSm(NPTS / 128, BATCH);
    dim3 gridAsm(NPTS / 32, BATCH);
    dim3 gridKnn(NPTS, BATCH);
    dim3 gridT(NPTS / 32, C / 32, BATCH);
    dim3 blkT(32, 8);

    zero_stats_kernel<<<1, 256>>>();
    transpose64_kernel<<<(BATCH * NPTS * CIN) / 256, 256>>>(feat1, feat1T);
    transpose64_kernel<<<(BATCH * NPTS * CIN) / 256, 256>>>(feat2, feat2T);

    tgemm_kernel<<<gridSm, 256, TG_SMEM>>>(t11_w, t11_b, feat1T, f1T, nullptr, nullptr, NPTS, CIN);
    tgemm_kernel<<<gridSm, 256, TG_SMEM>>>(t22_w, t22_b, feat2T, f2T, nullptr, nullptr, NPTS, CIN);
    tgemm_kernel<<<gridSm, 256, TG_SMEM>>>(t11_w, t11_b, feat2T, g1T, nullptr, nullptr, NPTS, CIN);
    tgemm_kernel<<<gridSm, 256, TG_SMEM>>>(t22_w, t22_b, feat1T, g2T, nullptr, nullptr, NPTS, CIN);

    knn_kernel<<<gridKnn, 256>>>(pc1, pc2, idx12);
    knn_kernel<<<gridKnn, 256>>>(pc2, pc1, idx21);

    // ---------------- cross 1 ----------------
    assemble_kernel<<<gridAsm, 128>>>(pc1, pc2, f1T, f2T, idx12, pos1_w, pos1_b, XA, STAT(0));
    finalize_kernel<<<1, 256>>>(STAT(0), gn1_g, gn1_b, SB(0), GN_INVCOUNT);
    tgemm_kernel<<<gridBig, 256, TG_SMEM>>>(m1a_w, m1a_b, XA, XB, SB(0), STAT(1), LBIG, C);
    finalize_kernel<<<1, 256>>>(STAT(1), m1a_g, m1a_bt, SB(1), GN_INVCOUNT);
    tgemm_kernel<<<gridBig, 256, TG_SMEM>>>(m1b_w, m1b_b, XB, XA, SB(1), STAT(2), LBIG, C);
    finalize_kernel<<<1, 256>>>(STAT(2), m1b_g, m1b_bt, SB(2), GN_INVCOUNT);
    maxpool_kernel<<<gridAsm, 128>>>(XA, SB(2), crossT, nullptr);
    tgemm_kernel<<<gridSm, 256, TG_SMEM>>>(t1_w, t1_b, crossT, f1nT, nullptr, nullptr, NPTS, C);
    lc2cl_kernel<<<gridT, blkT>>>(f1nT, out);

    // ---------------- cross 2 ----------------
    assemble_kernel<<<gridAsm, 128>>>(pc2, pc1, g1T, g2T, idx21, pos1_w, pos1_b, XA, STAT(3));
    finalize_kernel<<<1, 256>>>(STAT(3), gn1_g, gn1_b, SB(3), GN_INVCOUNT);
    tgemm_kernel<<<gridBig, 256, TG_SMEM>>>(m1a_w, m1a_b, XA, XB, SB(3), STAT(4), LBIG, C);
    finalize_kernel<<<1, 256>>>(STAT(4), m1a_g, m1a_bt, SB(4), GN_INVCOUNT);
    tgemm_kernel<<<gridBig, 256, TG_SMEM>>>(m1b_w, m1b_b, XB, XA, SB(4), STAT(5), LBIG, C);
    finalize_kernel<<<1, 256>>>(STAT(5), m1b_g, m1b_bt, SB(5), GN_INVCOUNT);
    maxpool_kernel<<<gridAsm, 128>>>(XA, SB(5), crossT, nullptr);
    tgemm_kernel<<<gridSm, 256, TG_SMEM>>>(t2_w, t2_b, crossT, f2nT, nullptr, nullptr, NPTS, C);
    lc2cl_kernel<<<gridT, blkT>>>(f2nT, out + BCN);

    // ---------------- cross 3 ----------------
    assemble_kernel<<<gridAsm, 128>>>(pc1, pc2, f1nT, f2nT, idx12, pos2_w, pos2_b, XA, STAT(6));
    finalize_kernel<<<1, 256>>>(STAT(6), gn2_g, gn2_b, SB(6), GN_INVCOUNT);
    tgemm_kernel<<<gridBig, 256, TG_SMEM>>>(m2a_w, m2a_b, XA, XB, SB(6), STAT(7), LBIG, C);
    finalize_kernel<<<1, 256>>>(STAT(7), m2a_g, m2a_bt, SB(7), GN_INVCOUNT);
    maxpool_kernel<<<gridAsm, 128>>>(XB, SB(7), nullptr, out + 2 * BCN);
}